// round 4
// baseline (speedup 1.0000x reference)
#include <cuda_runtime.h>
#include <cuda_bf16.h>

#define NPTS 8192
#define NB 4
#define NPAIRS (NPTS / 2)          // 4096 pairs per (arr,b)
#define BDIM 64
#define TA 8
#define A_PER_BLK (BDIM * TA)      // 512
#define NACH (NPTS / A_PER_BLK)    // 16
#define NBCH 16                    // B chunks of 512 points
#define CH_PAIRS (NPAIRS / NBCH)   // 256 pairs per chunk (8KB tile)
#define NITEMS (2 * NB * NACH * NBCH)   // 2048
#define NBLOCKS 1024
#define NCOMB 64

// Transformed B pairs: [arr][b][pair][4] = {x01,y01,z01,w01}; x01=(-2x0,-2x1), w01=(|b0|^2,|b1|^2)
__device__ unsigned long long g_bt[2][NB][NPAIRS][4];
// Final per-A min distance (clamped, >=0) as raw float bits (monotonic for uint atomicMin).
__device__ unsigned g_slot[2][NB][NPTS];
__device__ float g_part[NCOMB][4];
__device__ int g_ticket;
__device__ int g_done;

#define PACK2(dst, lo, hi) \
    asm("mov.b64 %0, {%1, %2};" : "=l"(dst) : "r"(__float_as_uint(lo)), "r"(__float_as_uint(hi)))
#define UNPACK2(lo, hi, src) \
    { unsigned _ulo, _uhi; \
      asm("mov.b64 {%0, %1}, %2;" : "=r"(_ulo), "=r"(_uhi) : "l"(src)); \
      lo = __uint_as_float(_ulo); hi = __uint_as_float(_uhi); }
#define FMA2(d, a, b, c) \
    asm("fma.rn.f32x2 %0, %1, %2, %3;" : "=l"(d) : "l"(a), "l"(b), "l"(c))
#define LDS_V2U64(r0, r1, addr) \
    asm volatile("ld.shared.v2.u64 {%0, %1}, [%2];" : "=l"(r0), "=l"(r1) : "r"(addr))

// k1: pre-transform B clouds into pair-SoA, init min slots, reset tickets.
__global__ __launch_bounds__(256) void transform_kernel(
    const float* __restrict__ xyz1,
    const float* __restrict__ xyz2)
{
    const int t = blockIdx.x * 256 + threadIdx.x;     // 0..32767
    if (t == 0) { g_ticket = 0; g_done = 0; }
    ((unsigned*)g_slot)[t]         = 0x7F800000u;     // +inf
    ((unsigned*)g_slot)[t + 32768] = 0x7F800000u;

    const int arr = t >> 14;
    const int rem = t & 16383;
    const int b = rem >> 12;
    const int j = rem & 4095;
    const float* src = (arr ? xyz2 : xyz1) + (size_t)(b * NPTS + 2 * j) * 3;
    float x0 = src[0], y0 = src[1], z0 = src[2];
    float x1 = src[3], y1 = src[4], z1 = src[5];

    unsigned long long X, Y, Z, W;
    PACK2(X, -2.0f * x0, -2.0f * x1);
    PACK2(Y, -2.0f * y0, -2.0f * y1);
    PACK2(Z, -2.0f * z0, -2.0f * z1);
    PACK2(W, x0 * x0 + y0 * y0 + z0 * z0, x1 * x1 + y1 * y1 + z1 * z1);
    unsigned long long* dst = &g_bt[arr][b][j][0];
    dst[0] = X; dst[1] = Y; dst[2] = Z; dst[3] = W;
}

// k2: persistent min-distance with dynamic work queue.
// Item = [dir|b|aChunk|bChunk] -> 512 A points x 512 B points.
__global__ __launch_bounds__(BDIM) void min_dist_kernel(
    const float* __restrict__ xyz1,
    const float* __restrict__ xyz2)
{
    __shared__ __align__(16) unsigned long long sB[CH_PAIRS * 4];  // 8KB
    __shared__ int sItem;

    const unsigned sbase = (unsigned)__cvta_generic_to_shared(sB);
    const int tid = threadIdx.x;

    for (;;) {
        if (tid == 0) sItem = atomicAdd(&g_ticket, 1);
        __syncthreads();                     // also guards sB reuse from prev item
        const int it = sItem;
        if (it >= NITEMS) break;

        const int bCh = it & (NBCH - 1);
        const int aCh = (it >> 4) & (NACH - 1);
        const int b   = (it >> 8) & (NB - 1);
        const int dir = it >> 10;

        // Load this item's B tile (256 pairs = 8KB).
        {
            const ulonglong2* src =
                (const ulonglong2*)&g_bt[1 - dir][b][bCh * CH_PAIRS][0];
            ulonglong2* dst = (ulonglong2*)sB;
            #pragma unroll
            for (int i = 0; i < (CH_PAIRS * 4) / 2 / BDIM; i++)
                dst[i * BDIM + tid] = src[i * BDIM + tid];
        }

        // Load this item's A registers.
        const float* Abase = ((dir == 0) ? xyz1 : xyz2) + (size_t)b * NPTS * 3;
        const int aBase = aCh * A_PER_BLK;
        unsigned long long AX[TA], AY[TA], AZ[TA];
        float s1[TA], best0[TA], best1[TA];
        #pragma unroll
        for (int k = 0; k < TA; k++) {
            const int a = aBase + k * BDIM + tid;
            float ax = Abase[a * 3 + 0];
            float ay = Abase[a * 3 + 1];
            float az = Abase[a * 3 + 2];
            PACK2(AX[k], ax, ax);
            PACK2(AY[k], ay, ay);
            PACK2(AZ[k], az, az);
            s1[k] = ax * ax + ay * ay + az * az;
            best0[k] = 3.402823e38f;
            best1[k] = 3.402823e38f;
        }
        __syncthreads();

        #pragma unroll 4
        for (int j = 0; j < CH_PAIRS; j++) {
            unsigned long long x01, y01, z01, w01;
            LDS_V2U64(x01, y01, sbase + j * 32);
            LDS_V2U64(z01, w01, sbase + j * 32 + 16);
            #pragma unroll
            for (int k = 0; k < TA; k++) {
                unsigned long long d;
                FMA2(d, x01, AX[k], w01);
                FMA2(d, y01, AY[k], d);
                FMA2(d, z01, AZ[k], d);
                float d0, d1;
                UNPACK2(d0, d1, d);
                best0[k] = fminf(best0[k], d0);
                best1[k] = fminf(best1[k], d1);
            }
        }

        // Epilogue: fold s1 + clamp, publish via uint atomicMin (non-negative floats).
        #pragma unroll
        for (int k = 0; k < TA; k++) {
            const int a = aBase + k * BDIM + tid;
            float d = fmaxf(fminf(best0[k], best1[k]) + s1[k], 0.0f);
            atomicMin(&g_slot[dir][b][a], __float_as_uint(d));
        }
    }
}

// k3: weighted reduction; last block folds the 64 partials (fixed order, deterministic).
__global__ __launch_bounds__(256) void combine_kernel(
    const float* __restrict__ w1,
    const float* __restrict__ w2,
    float* __restrict__ out)
{
    __shared__ float s[4][8];
    __shared__ int sLast;

    float num[2] = {0.f, 0.f}, den[2] = {0.f, 0.f};
    const int g = blockIdx.x * 256 + threadIdx.x;     // 0..16383

    #pragma unroll
    for (int rep = 0; rep < 2; rep++) {
        const int i = g + rep * 16384;                 // 0..32767 = b*8192+a
        #pragma unroll
        for (int dir = 0; dir < 2; dir++) {
            const float d = __uint_as_float(((const unsigned*)g_slot)[dir * 32768 + i]);
            const float w = ((dir == 0) ? w1 : w2)[i];
            num[dir] = fmaf(d, w, num[dir]);
            den[dir] += w;
        }
    }

    #pragma unroll
    for (int off = 16; off > 0; off >>= 1) {
        num[0] += __shfl_down_sync(0xffffffffu, num[0], off);
        den[0] += __shfl_down_sync(0xffffffffu, den[0], off);
        num[1] += __shfl_down_sync(0xffffffffu, num[1], off);
        den[1] += __shfl_down_sync(0xffffffffu, den[1], off);
    }
    const int wid = threadIdx.x >> 5;
    if ((threadIdx.x & 31) == 0) {
        s[0][wid] = num[0]; s[1][wid] = den[0];
        s[2][wid] = num[1]; s[3][wid] = den[1];
    }
    __syncthreads();
    if (threadIdx.x == 0) {
        float a0 = 0, a1 = 0, a2 = 0, a3 = 0;
        #pragma unroll
        for (int i = 0; i < 8; i++) {
            a0 += s[0][i]; a1 += s[1][i]; a2 += s[2][i]; a3 += s[3][i];
        }
        g_part[blockIdx.x][0] = a0; g_part[blockIdx.x][1] = a1;
        g_part[blockIdx.x][2] = a2; g_part[blockIdx.x][3] = a3;
        __threadfence();
        sLast = (atomicAdd(&g_done, 1) == NCOMB - 1);
    }
    __syncthreads();

    if (sLast && threadIdx.x == 0) {
        volatile float (*gp)[4] = g_part;
        float N0 = 0, D0 = 0, N1 = 0, D1 = 0;
        for (int i = 0; i < NCOMB; i++) {
            N0 += gp[i][0]; D0 += gp[i][1]; N1 += gp[i][2]; D1 += gp[i][3];
        }
        out[0] = 0.5f * (N0 / D0 + N1 / D1);
    }
}

extern "C" void kernel_launch(void* const* d_in, const int* in_sizes, int n_in,
                              void* d_out, int out_size)
{
    const float* xyz1 = (const float*)d_in[0];
    const float* xyz2 = (const float*)d_in[1];
    const float* w1   = (const float*)d_in[2];
    const float* w2   = (const float*)d_in[3];
    float* out        = (float*)d_out;

    transform_kernel<<<128, 256>>>(xyz1, xyz2);
    min_dist_kernel<<<NBLOCKS, BDIM>>>(xyz1, xyz2);
    combine_kernel<<<NCOMB, 256>>>(w1, w2, out);
}

// round 5
// speedup vs baseline: 1.1083x; 1.1083x over previous
#include <cuda_runtime.h>
#include <cuda_bf16.h>

#define NPTS 8192
#define NB 4
#define BDIM 64
#define TA 4
#define A_PER_BLK (BDIM * TA)          // 256
#define NACH (NPTS / A_PER_BLK)        // 32
#define NBCH 8                         // B chunks of 1024 points
#define BCH_PTS (NPTS / NBCH)          // 1024
#define TILE_PTS 512
#define TILE_PAIRS (TILE_PTS / 2)      // 256 pairs -> 8KB smem
#define TILES_PER_CH (BCH_PTS / TILE_PTS)  // 2
#define NBLOCKS (2 * NB * NACH * NBCH)     // 2048
#define NCOMB 64

// Per-(dir,b,a) partial mins across the 8 B-chunks (bCh contiguous -> float4-loadable).
__device__ float g_min[2][NB][NPTS][NBCH];
__device__ float g_part[NCOMB][4];
__device__ int g_done;

#define PACK2(dst, lo, hi) \
    asm("mov.b64 %0, {%1, %2};" : "=l"(dst) : "r"(__float_as_uint(lo)), "r"(__float_as_uint(hi)))
#define UNPACK2(lo, hi, src) \
    { unsigned _ulo, _uhi; \
      asm("mov.b64 {%0, %1}, %2;" : "=r"(_ulo), "=r"(_uhi) : "l"(src)); \
      lo = __uint_as_float(_ulo); hi = __uint_as_float(_uhi); }
#define FMA2(d, a, b, c) \
    asm("fma.rn.f32x2 %0, %1, %2, %3;" : "=l"(d) : "l"(a), "l"(b), "l"(c))
#define LDS_V2U64(r0, r1, addr) \
    asm volatile("ld.shared.v2.u64 {%0, %1}, [%2];" : "=l"(r0), "=l"(r1) : "r"(addr))

// k1: min-distance. Block = 256 A points x one 1024-pt B chunk; B transformed
// in-kernel into pair-SoA smem tiles {(-2x0,-2x1),(-2y0,-2y1),(-2z0,-2z1),(w0,w1)}.
__global__ __launch_bounds__(BDIM) void min_dist_kernel(
    const float* __restrict__ xyz1,
    const float* __restrict__ xyz2)
{
    __shared__ __align__(16) unsigned long long sB[TILE_PAIRS * 4];  // 8KB
    float4* sXY = (float4*)sB;                                        // [256] pairs: x01,y01
    // layout per pair j: sB[4j..4j+3] = x01,y01,z01,w01

    const int bx = blockIdx.x;
    if (bx == 0 && threadIdx.x == 0) g_done = 0;   // reset for combine (stream-ordered)

    const int aCh = bx & (NACH - 1);
    const int bCh = (bx >> 5) & (NBCH - 1);
    const int b   = (bx >> 8) & (NB - 1);
    const int dir = bx >> 10;

    const float* Abase = ((dir == 0) ? xyz1 : xyz2) + (size_t)b * NPTS * 3;
    const float* Bbase = ((dir == 0) ? xyz2 : xyz1) + (size_t)b * NPTS * 3;

    const int aBase = aCh * A_PER_BLK;
    const int tid = threadIdx.x;

    unsigned long long AX[TA], AY[TA], AZ[TA];
    float s1[TA], best0[TA], best1[TA];
    #pragma unroll
    for (int k = 0; k < TA; k++) {
        const int a = aBase + k * BDIM + tid;
        float ax = Abase[a * 3 + 0];
        float ay = Abase[a * 3 + 1];
        float az = Abase[a * 3 + 2];
        PACK2(AX[k], ax, ax);
        PACK2(AY[k], ay, ay);
        PACK2(AZ[k], az, az);
        s1[k] = ax * ax + ay * ay + az * az;
        best0[k] = 3.402823e38f;
        best1[k] = 3.402823e38f;
    }

    const unsigned sbase = (unsigned)__cvta_generic_to_shared(sB);

    for (int tile = 0; tile < TILES_PER_CH; tile++) {
        const int p0 = bCh * BCH_PTS + tile * TILE_PTS;
        __syncthreads();
        // Transform this tile's 512 raw B points (L1/L2-resident) into pair-SoA.
        {
            const float2* B2 = (const float2*)(Bbase + (size_t)p0 * 3);
            #pragma unroll
            for (int i = 0; i < TILE_PAIRS / BDIM; i++) {   // 4 pairs/thread
                const int j = i * BDIM + tid;
                float2 q0 = B2[3 * j + 0];   // x0 y0
                float2 q1 = B2[3 * j + 1];   // z0 x1
                float2 q2 = B2[3 * j + 2];   // y1 z1
                float w0 = q0.x * q0.x + q0.y * q0.y + q1.x * q1.x;
                float w1 = q1.y * q1.y + q2.x * q2.x + q2.y * q2.y;
                ((float4*)sB)[2 * j + 0] =
                    make_float4(-2.0f * q0.x, -2.0f * q1.y, -2.0f * q0.y, -2.0f * q2.x);
                ((float4*)sB)[2 * j + 1] =
                    make_float4(-2.0f * q1.x, -2.0f * q2.y, w0, w1);
            }
        }
        __syncthreads();

        #pragma unroll 4
        for (int j = 0; j < TILE_PAIRS; j++) {
            unsigned long long x01, y01, z01, w01;
            LDS_V2U64(x01, y01, sbase + j * 32);
            LDS_V2U64(z01, w01, sbase + j * 32 + 16);
            #pragma unroll
            for (int k = 0; k < TA; k++) {
                unsigned long long d;
                FMA2(d, x01, AX[k], w01);
                FMA2(d, y01, AY[k], d);
                FMA2(d, z01, AZ[k], d);
                float d0, d1;
                UNPACK2(d0, d1, d);
                best0[k] = fminf(best0[k], d0);
                best1[k] = fminf(best1[k], d1);
            }
        }
    }

    // Publish per-chunk partial min (no atomics): clamp(s1 + min, 0).
    #pragma unroll
    for (int k = 0; k < TA; k++) {
        const int a = aBase + k * BDIM + tid;
        g_min[dir][b][a][bCh] = fmaxf(fminf(best0[k], best1[k]) + s1[k], 0.0f);
    }
}

// k2: fold 8 partials per slot, weight, fixed-order reduce; last block finishes.
__global__ __launch_bounds__(256) void combine_kernel(
    const float* __restrict__ w1,
    const float* __restrict__ w2,
    float* __restrict__ out)
{
    __shared__ float s[4][8];
    __shared__ int sLast;

    float num[2] = {0.f, 0.f}, den[2] = {0.f, 0.f};
    const int g = blockIdx.x * 256 + threadIdx.x;     // 0..16383

    #pragma unroll
    for (int rep = 0; rep < 4; rep++) {
        const int i = g + rep * 16384;                 // 0..65535 slots
        const int dir = rep >> 1;                      // slots: dir-major
        const int rem = i & 32767;                     // b*8192+a
        const float4* p = (const float4*)&g_min[0][0][0][0] + (size_t)i * 2;
        float4 v0 = p[0];
        float4 v1 = p[1];
        float m = fminf(fminf(fminf(v0.x, v0.y), fminf(v0.z, v0.w)),
                        fminf(fminf(v1.x, v1.y), fminf(v1.z, v1.w)));
        const float w = ((dir == 0) ? w1 : w2)[rem];
        num[dir] = fmaf(m, w, num[dir]);
        den[dir] += w;
    }

    #pragma unroll
    for (int off = 16; off > 0; off >>= 1) {
        num[0] += __shfl_down_sync(0xffffffffu, num[0], off);
        den[0] += __shfl_down_sync(0xffffffffu, den[0], off);
        num[1] += __shfl_down_sync(0xffffffffu, num[1], off);
        den[1] += __shfl_down_sync(0xffffffffu, den[1], off);
    }
    const int wid = threadIdx.x >> 5;
    if ((threadIdx.x & 31) == 0) {
        s[0][wid] = num[0]; s[1][wid] = den[0];
        s[2][wid] = num[1]; s[3][wid] = den[1];
    }
    __syncthreads();
    if (threadIdx.x == 0) {
        float a0 = 0, a1 = 0, a2 = 0, a3 = 0;
        #pragma unroll
        for (int i = 0; i < 8; i++) {
            a0 += s[0][i]; a1 += s[1][i]; a2 += s[2][i]; a3 += s[3][i];
        }
        g_part[blockIdx.x][0] = a0; g_part[blockIdx.x][1] = a1;
        g_part[blockIdx.x][2] = a2; g_part[blockIdx.x][3] = a3;
        __threadfence();
        sLast = (atomicAdd(&g_done, 1) == NCOMB - 1);
    }
    __syncthreads();

    if (sLast && threadIdx.x == 0) {
        volatile float (*gp)[4] = g_part;
        float N0 = 0, D0 = 0, N1 = 0, D1 = 0;
        for (int i = 0; i < NCOMB; i++) {
            N0 += gp[i][0]; D0 += gp[i][1]; N1 += gp[i][2]; D1 += gp[i][3];
        }
        out[0] = 0.5f * (N0 / D0 + N1 / D1);
    }
}

extern "C" void kernel_launch(void* const* d_in, const int* in_sizes, int n_in,
                              void* d_out, int out_size)
{
    const float* xyz1 = (const float*)d_in[0];
    const float* xyz2 = (const float*)d_in[1];
    const float* w1   = (const float*)d_in[2];
    const float* w2   = (const float*)d_in[3];
    float* out        = (float*)d_out;

    min_dist_kernel<<<NBLOCKS, BDIM>>>(xyz1, xyz2);
    combine_kernel<<<NCOMB, 256>>>(w1, w2, out);
}

// round 6
// speedup vs baseline: 1.1393x; 1.0280x over previous
#include <cuda_runtime.h>
#include <cuda_bf16.h>

#define NPTS 8192
#define NB 4
#define NPAIRS (NPTS / 2)              // 4096 pairs per (arr,b)
#define BDIM 64
#define TA 4
#define A_PER_BLK (BDIM * TA)          // 256
#define NACH (NPTS / A_PER_BLK)        // 32
#define NBCH 8                         // B chunks of 1024 points
#define BCH_PTS (NPTS / NBCH)          // 1024
#define TILE_PAIRS 256                 // 512 B points -> 8KB smem
#define TILES_PER_CH (BCH_PTS / (2 * TILE_PAIRS))   // 2
#define NBLOCKS (2 * NB * NACH * NBCH)              // 2048
#define NCOMB 256

// Transformed B pairs: [arr][b][pair][4] = {x01,y01,z01,w01}
__device__ unsigned long long g_bt[2][NB][NPAIRS][4];
// Per-(dir,b,a) partial mins across 8 B-chunks (clamped, s1 folded in).
__device__ float g_min[2][NB][NPTS][NBCH];
__device__ float g_part[NCOMB][4];
__device__ int g_done;

#define PACK2(dst, lo, hi) \
    asm("mov.b64 %0, {%1, %2};" : "=l"(dst) : "r"(__float_as_uint(lo)), "r"(__float_as_uint(hi)))
#define UNPACK2(lo, hi, src) \
    { unsigned _ulo, _uhi; \
      asm("mov.b64 {%0, %1}, %2;" : "=r"(_ulo), "=r"(_uhi) : "l"(src)); \
      lo = __uint_as_float(_ulo); hi = __uint_as_float(_uhi); }
#define FMA2(d, a, b, c) \
    asm("fma.rn.f32x2 %0, %1, %2, %3;" : "=l"(d) : "l"(a), "l"(b), "l"(c))
#define LDS_V2U64(r0, r1, addr) \
    asm volatile("ld.shared.v2.u64 {%0, %1}, [%2];" : "=l"(r0), "=l"(r1) : "r"(addr))

// k1: pre-transform both clouds into pair-SoA; reset combine flag.
__global__ __launch_bounds__(256) void transform_kernel(
    const float* __restrict__ xyz1,
    const float* __restrict__ xyz2)
{
    const int t = blockIdx.x * 256 + threadIdx.x;     // 0..32767
    if (t == 0) g_done = 0;

    const int arr = t >> 14;
    const int rem = t & 16383;
    const int b = rem >> 12;
    const int j = rem & 4095;
    const float* src = (arr ? xyz2 : xyz1) + (size_t)(b * NPTS + 2 * j) * 3;
    float x0 = src[0], y0 = src[1], z0 = src[2];
    float x1 = src[3], y1 = src[4], z1 = src[5];

    unsigned long long X, Y, Z, W;
    PACK2(X, -2.0f * x0, -2.0f * x1);
    PACK2(Y, -2.0f * y0, -2.0f * y1);
    PACK2(Z, -2.0f * z0, -2.0f * z1);
    PACK2(W, x0 * x0 + y0 * y0 + z0 * z0, x1 * x1 + y1 * y1 + z1 * z1);
    unsigned long long* dst = &g_bt[arr][b][j][0];
    dst[0] = X; dst[1] = Y; dst[2] = Z; dst[3] = W;
}

// k2: min-distance (R3 mainloop). Block = 256 A x one 1024-pt B chunk.
__global__ __launch_bounds__(BDIM) void min_dist_kernel(
    const float* __restrict__ xyz1,
    const float* __restrict__ xyz2)
{
    __shared__ __align__(16) unsigned long long sB[TILE_PAIRS * 4];  // 8KB

    const int bx = blockIdx.x;
    const int aCh = bx & (NACH - 1);
    const int bCh = (bx >> 5) & (NBCH - 1);
    const int b   = (bx >> 8) & (NB - 1);
    const int dir = bx >> 10;

    const float* Abase = ((dir == 0) ? xyz1 : xyz2) + (size_t)b * NPTS * 3;
    const unsigned long long* bt = &g_bt[1 - dir][b][0][0];

    const int aBase = aCh * A_PER_BLK;
    const int tid = threadIdx.x;

    unsigned long long AX[TA], AY[TA], AZ[TA];
    float s1[TA], best0[TA], best1[TA];
    #pragma unroll
    for (int k = 0; k < TA; k++) {
        const int a = aBase + k * BDIM + tid;
        float ax = Abase[a * 3 + 0];
        float ay = Abase[a * 3 + 1];
        float az = Abase[a * 3 + 2];
        PACK2(AX[k], ax, ax);
        PACK2(AY[k], ay, ay);
        PACK2(AZ[k], az, az);
        s1[k] = ax * ax + ay * ay + az * az;
        best0[k] = 3.402823e38f;
        best1[k] = 3.402823e38f;
    }

    const unsigned sbase = (unsigned)__cvta_generic_to_shared(sB);

    for (int tile = 0; tile < TILES_PER_CH; tile++) {
        const int pair0 = bCh * (BCH_PTS / 2) + tile * TILE_PAIRS;
        __syncthreads();
        {
            const ulonglong2* src = (const ulonglong2*)(bt + (size_t)pair0 * 4);
            ulonglong2* dst = (ulonglong2*)sB;
            #pragma unroll
            for (int i = 0; i < (TILE_PAIRS * 4) / 2 / BDIM; i++)
                dst[i * BDIM + tid] = src[i * BDIM + tid];
        }
        __syncthreads();

        #pragma unroll 4
        for (int j = 0; j < TILE_PAIRS; j++) {
            unsigned long long x01, y01, z01, w01;
            LDS_V2U64(x01, y01, sbase + j * 32);
            LDS_V2U64(z01, w01, sbase + j * 32 + 16);
            #pragma unroll
            for (int k = 0; k < TA; k++) {
                unsigned long long d;
                FMA2(d, x01, AX[k], w01);
                FMA2(d, y01, AY[k], d);
                FMA2(d, z01, AZ[k], d);
                float d0, d1;
                UNPACK2(d0, d1, d);
                best0[k] = fminf(best0[k], d0);
                best1[k] = fminf(best1[k], d1);
            }
        }
    }

    // Epilogue: fold s1 + clamp, store per-chunk partial min (no atomics).
    #pragma unroll
    for (int k = 0; k < TA; k++) {
        const int a = aBase + k * BDIM + tid;
        g_min[dir][b][a][bCh] = fmaxf(fminf(best0[k], best1[k]) + s1[k], 0.0f);
    }
}

// k3: fold 8 partials per slot, weight, reduce; last block finishes (fixed order).
__global__ __launch_bounds__(256) void combine_kernel(
    const float* __restrict__ w1,
    const float* __restrict__ w2,
    float* __restrict__ out)
{
    __shared__ float s[4][8];
    __shared__ int sLast;

    const int g = blockIdx.x * 256 + threadIdx.x;     // 0..65535 = one slot
    const int dir = g >> 15;
    const int rem = g & 32767;                        // b*8192+a

    const float4* p = (const float4*)&g_min[0][0][0][0] + (size_t)g * 2;
    float4 v0 = p[0];
    float4 v1 = p[1];
    float m = fminf(fminf(fminf(v0.x, v0.y), fminf(v0.z, v0.w)),
                    fminf(fminf(v1.x, v1.y), fminf(v1.z, v1.w)));
    const float w = ((dir == 0) ? w1 : w2)[rem];
    float num0 = (dir == 0) ? m * w : 0.f;
    float den0 = (dir == 0) ? w : 0.f;
    float num1 = (dir == 0) ? 0.f : m * w;
    float den1 = (dir == 0) ? 0.f : w;

    #pragma unroll
    for (int off = 16; off > 0; off >>= 1) {
        num0 += __shfl_down_sync(0xffffffffu, num0, off);
        den0 += __shfl_down_sync(0xffffffffu, den0, off);
        num1 += __shfl_down_sync(0xffffffffu, num1, off);
        den1 += __shfl_down_sync(0xffffffffu, den1, off);
    }
    const int wid = threadIdx.x >> 5;
    if ((threadIdx.x & 31) == 0) {
        s[0][wid] = num0; s[1][wid] = den0;
        s[2][wid] = num1; s[3][wid] = den1;
    }
    __syncthreads();
    if (threadIdx.x == 0) {
        float a0 = 0, a1 = 0, a2 = 0, a3 = 0;
        #pragma unroll
        for (int i = 0; i < 8; i++) {
            a0 += s[0][i]; a1 += s[1][i]; a2 += s[2][i]; a3 += s[3][i];
        }
        g_part[blockIdx.x][0] = a0; g_part[blockIdx.x][1] = a1;
        g_part[blockIdx.x][2] = a2; g_part[blockIdx.x][3] = a3;
        __threadfence();
        sLast = (atomicAdd(&g_done, 1) == NCOMB - 1);
    }
    __syncthreads();

    if (sLast) {
        __threadfence();
        // Parallel fold of the 256 partials by the last block's 256 threads.
        volatile float (*gp)[4] = g_part;
        float a0 = gp[threadIdx.x][0];
        float a1 = gp[threadIdx.x][1];
        float a2 = gp[threadIdx.x][2];
        float a3 = gp[threadIdx.x][3];
        #pragma unroll
        for (int off = 16; off > 0; off >>= 1) {
            a0 += __shfl_down_sync(0xffffffffu, a0, off);
            a1 += __shfl_down_sync(0xffffffffu, a1, off);
            a2 += __shfl_down_sync(0xffffffffu, a2, off);
            a3 += __shfl_down_sync(0xffffffffu, a3, off);
        }
        __syncthreads();   // reuse s[][] safely
        if ((threadIdx.x & 31) == 0) {
            s[0][wid] = a0; s[1][wid] = a1; s[2][wid] = a2; s[3][wid] = a3;
        }
        __syncthreads();
        if (threadIdx.x == 0) {
            float N0 = 0, D0 = 0, N1 = 0, D1 = 0;
            #pragma unroll
            for (int i = 0; i < 8; i++) {
                N0 += s[0][i]; D0 += s[1][i]; N1 += s[2][i]; D1 += s[3][i];
            }
            out[0] = 0.5f * (N0 / D0 + N1 / D1);
        }
    }
}

extern "C" void kernel_launch(void* const* d_in, const int* in_sizes, int n_in,
                              void* d_out, int out_size)
{
    const float* xyz1 = (const float*)d_in[0];
    const float* xyz2 = (const float*)d_in[1];
    const float* w1   = (const float*)d_in[2];
    const float* w2   = (const float*)d_in[3];
    float* out        = (float*)d_out;

    transform_kernel<<<128, 256>>>(xyz1, xyz2);
    min_dist_kernel<<<NBLOCKS, BDIM>>>(xyz1, xyz2);
    combine_kernel<<<NCOMB, 256>>>(w1, w2, out);
}

// round 7
// speedup vs baseline: 1.1616x; 1.0196x over previous
#include <cuda_runtime.h>
#include <cuda_bf16.h>

#define NPTS 8192
#define NB 4
#define NPAIRS (NPTS / 2)              // 4096 pairs per (arr,b)
#define BDIM 128
#define TA 4
#define A_PER_BLK (BDIM * TA)          // 512
#define NACH (NPTS / A_PER_BLK)        // 16
#define NBCH 8                         // B chunks of 1024 points
#define BCH_PTS (NPTS / NBCH)          // 1024
#define TILE_PAIRS 256                 // 512 B points -> 8KB smem
#define TILES_PER_CH (BCH_PTS / (2 * TILE_PAIRS))   // 2
#define NBLOCKS (2 * NB * NACH * NBCH)              // 1024
#define NCOMB 256

// Transformed B pairs: [arr][b][pair][4] = {x01,y01,z01,w01}
__device__ unsigned long long g_bt[2][NB][NPAIRS][4];
// Per-(dir,b,a) partial mins across 8 B-chunks (clamped, s1 folded in).
__device__ float g_min[2][NB][NPTS][NBCH];
__device__ float g_part[NCOMB][4];
__device__ int g_done;

#define PACK2(dst, lo, hi) \
    asm("mov.b64 %0, {%1, %2};" : "=l"(dst) : "r"(__float_as_uint(lo)), "r"(__float_as_uint(hi)))
#define UNPACK2(lo, hi, src) \
    { unsigned _ulo, _uhi; \
      asm("mov.b64 {%0, %1}, %2;" : "=r"(_ulo), "=r"(_uhi) : "l"(src)); \
      lo = __uint_as_float(_ulo); hi = __uint_as_float(_uhi); }
#define FMA2(d, a, b, c) \
    asm("fma.rn.f32x2 %0, %1, %2, %3;" : "=l"(d) : "l"(a), "l"(b), "l"(c))
#define LDS_V2U64(r0, r1, addr) \
    asm volatile("ld.shared.v2.u64 {%0, %1}, [%2];" : "=l"(r0), "=l"(r1) : "r"(addr))

// k1: pre-transform both clouds into pair-SoA; reset combine flag.
__global__ __launch_bounds__(256) void transform_kernel(
    const float* __restrict__ xyz1,
    const float* __restrict__ xyz2)
{
    const int t = blockIdx.x * 256 + threadIdx.x;     // 0..32767
    if (t == 0) g_done = 0;

    const int arr = t >> 14;
    const int rem = t & 16383;
    const int b = rem >> 12;
    const int j = rem & 4095;
    const float* src = (arr ? xyz2 : xyz1) + (size_t)(b * NPTS + 2 * j) * 3;
    float x0 = src[0], y0 = src[1], z0 = src[2];
    float x1 = src[3], y1 = src[4], z1 = src[5];

    unsigned long long X, Y, Z, W;
    PACK2(X, -2.0f * x0, -2.0f * x1);
    PACK2(Y, -2.0f * y0, -2.0f * y1);
    PACK2(Z, -2.0f * z0, -2.0f * z1);
    PACK2(W, x0 * x0 + y0 * y0 + z0 * z0, x1 * x1 + y1 * y1 + z1 * z1);
    unsigned long long* dst = &g_bt[arr][b][j][0];
    dst[0] = X; dst[1] = Y; dst[2] = Z; dst[3] = W;
}

// k2: min-distance. Block = 512 A points (4 warps -> all 4 SMSPs) x one 1024-pt B chunk.
__global__ __launch_bounds__(BDIM) void min_dist_kernel(
    const float* __restrict__ xyz1,
    const float* __restrict__ xyz2)
{
    __shared__ __align__(16) unsigned long long sB[TILE_PAIRS * 4];  // 8KB

    const int bx = blockIdx.x;
    const int aCh = bx & (NACH - 1);
    const int bCh = (bx >> 4) & (NBCH - 1);
    const int b   = (bx >> 7) & (NB - 1);
    const int dir = bx >> 9;

    const float* Abase = ((dir == 0) ? xyz1 : xyz2) + (size_t)b * NPTS * 3;
    const unsigned long long* bt = &g_bt[1 - dir][b][0][0];

    const int aBase = aCh * A_PER_BLK;
    const int tid = threadIdx.x;

    unsigned long long AX[TA], AY[TA], AZ[TA];
    float s1[TA], best0[TA], best1[TA];
    #pragma unroll
    for (int k = 0; k < TA; k++) {
        const int a = aBase + k * BDIM + tid;
        float ax = Abase[a * 3 + 0];
        float ay = Abase[a * 3 + 1];
        float az = Abase[a * 3 + 2];
        PACK2(AX[k], ax, ax);
        PACK2(AY[k], ay, ay);
        PACK2(AZ[k], az, az);
        s1[k] = ax * ax + ay * ay + az * az;
        best0[k] = 3.402823e38f;
        best1[k] = 3.402823e38f;
    }

    const unsigned sbase = (unsigned)__cvta_generic_to_shared(sB);

    for (int tile = 0; tile < TILES_PER_CH; tile++) {
        const int pair0 = bCh * (BCH_PTS / 2) + tile * TILE_PAIRS;
        __syncthreads();
        {
            const ulonglong2* src = (const ulonglong2*)(bt + (size_t)pair0 * 4);
            ulonglong2* dst = (ulonglong2*)sB;
            #pragma unroll
            for (int i = 0; i < (TILE_PAIRS * 4) / 2 / BDIM; i++)   // 4 iters
                dst[i * BDIM + tid] = src[i * BDIM + tid];
        }
        __syncthreads();

        #pragma unroll 4
        for (int j = 0; j < TILE_PAIRS; j++) {
            unsigned long long x01, y01, z01, w01;
            LDS_V2U64(x01, y01, sbase + j * 32);
            LDS_V2U64(z01, w01, sbase + j * 32 + 16);
            #pragma unroll
            for (int k = 0; k < TA; k++) {
                unsigned long long d;
                FMA2(d, x01, AX[k], w01);
                FMA2(d, y01, AY[k], d);
                FMA2(d, z01, AZ[k], d);
                float d0, d1;
                UNPACK2(d0, d1, d);
                best0[k] = fminf(best0[k], d0);
                best1[k] = fminf(best1[k], d1);
            }
        }
    }

    // Epilogue: fold s1 + clamp, store per-chunk partial min (no atomics).
    #pragma unroll
    for (int k = 0; k < TA; k++) {
        const int a = aBase + k * BDIM + tid;
        g_min[dir][b][a][bCh] = fmaxf(fminf(best0[k], best1[k]) + s1[k], 0.0f);
    }
}

// k3: fold 8 partials per slot, weight, reduce; last block finishes (fixed order).
__global__ __launch_bounds__(256) void combine_kernel(
    const float* __restrict__ w1,
    const float* __restrict__ w2,
    float* __restrict__ out)
{
    __shared__ float s[4][8];
    __shared__ int sLast;

    const int g = blockIdx.x * 256 + threadIdx.x;     // 0..65535 = one slot
    const int dir = g >> 15;
    const int rem = g & 32767;                        // b*8192+a

    const float4* p = (const float4*)&g_min[0][0][0][0] + (size_t)g * 2;
    float4 v0 = p[0];
    float4 v1 = p[1];
    float m = fminf(fminf(fminf(v0.x, v0.y), fminf(v0.z, v0.w)),
                    fminf(fminf(v1.x, v1.y), fminf(v1.z, v1.w)));
    const float w = ((dir == 0) ? w1 : w2)[rem];
    float num0 = (dir == 0) ? m * w : 0.f;
    float den0 = (dir == 0) ? w : 0.f;
    float num1 = (dir == 0) ? 0.f : m * w;
    float den1 = (dir == 0) ? 0.f : w;

    #pragma unroll
    for (int off = 16; off > 0; off >>= 1) {
        num0 += __shfl_down_sync(0xffffffffu, num0, off);
        den0 += __shfl_down_sync(0xffffffffu, den0, off);
        num1 += __shfl_down_sync(0xffffffffu, num1, off);
        den1 += __shfl_down_sync(0xffffffffu, den1, off);
    }
    const int wid = threadIdx.x >> 5;
    if ((threadIdx.x & 31) == 0) {
        s[0][wid] = num0; s[1][wid] = den0;
        s[2][wid] = num1; s[3][wid] = den1;
    }
    __syncthreads();
    if (threadIdx.x == 0) {
        float a0 = 0, a1 = 0, a2 = 0, a3 = 0;
        #pragma unroll
        for (int i = 0; i < 8; i++) {
            a0 += s[0][i]; a1 += s[1][i]; a2 += s[2][i]; a3 += s[3][i];
        }
        g_part[blockIdx.x][0] = a0; g_part[blockIdx.x][1] = a1;
        g_part[blockIdx.x][2] = a2; g_part[blockIdx.x][3] = a3;
        __threadfence();
        sLast = (atomicAdd(&g_done, 1) == NCOMB - 1);
    }
    __syncthreads();

    if (sLast) {
        __threadfence();
        volatile float (*gp)[4] = g_part;
        float a0 = gp[threadIdx.x][0];
        float a1 = gp[threadIdx.x][1];
        float a2 = gp[threadIdx.x][2];
        float a3 = gp[threadIdx.x][3];
        #pragma unroll
        for (int off = 16; off > 0; off >>= 1) {
            a0 += __shfl_down_sync(0xffffffffu, a0, off);
            a1 += __shfl_down_sync(0xffffffffu, a1, off);
            a2 += __shfl_down_sync(0xffffffffu, a2, off);
            a3 += __shfl_down_sync(0xffffffffu, a3, off);
        }
        __syncthreads();
        if ((threadIdx.x & 31) == 0) {
            s[0][wid] = a0; s[1][wid] = a1; s[2][wid] = a2; s[3][wid] = a3;
        }
        __syncthreads();
        if (threadIdx.x == 0) {
            float N0 = 0, D0 = 0, N1 = 0, D1 = 0;
            #pragma unroll
            for (int i = 0; i < 8; i++) {
                N0 += s[0][i]; D0 += s[1][i]; N1 += s[2][i]; D1 += s[3][i];
            }
            out[0] = 0.5f * (N0 / D0 + N1 / D1);
        }
    }
}

extern "C" void kernel_launch(void* const* d_in, const int* in_sizes, int n_in,
                              void* d_out, int out_size)
{
    const float* xyz1 = (const float*)d_in[0];
    const float* xyz2 = (const float*)d_in[1];
    const float* w1   = (const float*)d_in[2];
    const float* w2   = (const float*)d_in[3];
    float* out        = (float*)d_out;

    transform_kernel<<<128, 256>>>(xyz1, xyz2);
    min_dist_kernel<<<NBLOCKS, BDIM>>>(xyz1, xyz2);
    combine_kernel<<<NCOMB, 256>>>(w1, w2, out);
}